// round 3
// baseline (speedup 1.0000x reference)
#include <cuda_runtime.h>
#include <math.h>
#include <stdint.h>

// Problem constants
#define B   8
#define NG  5
#define NL  75
#define NF  196
#define C   640
#define NT  (NL*NF)          // 14700 local tokens per batch
#define NMEAN_DEN (NG + NT)  // 14705
#define INV_ALPHA 10.0f
#define L2EPS 1e-12f

// ---- scratch layout (floats) in one __device__ global (no cudaMalloc allowed) ----
#define OFF_SG     0                        // B*C   raw sum of global_f over ng
#define OFF_SL     (OFF_SG + B*C)           // B*C   raw sum of local_f over nl*nf
#define OFF_GPROJ  (OFF_SL + B*C)           // B*NG*C  Wq @ global tokens
#define OFF_M1     (OFF_GPROJ + B*NG*C)     // B*C   Wq @ sum_g
#define OFF_M2     (OFF_M1 + B*C)           // B*C   Wk @ sum_l
#define OFF_MEAN   (OFF_M2 + B*C)           // B*C
#define OFF_GHAT   (OFF_MEAN + B*C)         // B*NG*C  normalized g
#define OFF_NORM2  (OFF_GHAT + B*NG*C)      // B*NT    ||Wk x - mean||^2 (atomic)
#define OFF_DOTS   (OFF_NORM2 + B*NT)       // B*NT*NG dots with ghat (atomic)
#define SCRATCH_FLOATS (OFF_DOTS + B*NT*NG) // 782,400 floats ~ 3.06 MB

__device__ float g_scratch[SCRATCH_FLOATS];

// ---------------------------------------------------------------------------
// Kernel 0: zero the scratch (atomically-accumulated parts need it each call)
// ---------------------------------------------------------------------------
__global__ void zero_k() {
    for (int i = blockIdx.x * blockDim.x + threadIdx.x; i < SCRATCH_FLOATS;
         i += gridDim.x * blockDim.x)
        g_scratch[i] = 0.0f;
}

// ---------------------------------------------------------------------------
// Kernel 1a: sum global_f over ng  -> s_g[b][c]
// ---------------------------------------------------------------------------
__global__ void sum_global_k(const float* __restrict__ gf) {
    int b = blockIdx.x;
    int c = threadIdx.x;   // blockDim = C = 640
    float acc = 0.f;
#pragma unroll
    for (int g = 0; g < NG; g++) acc += gf[(b * NG + g) * C + c];
    g_scratch[OFF_SG + b * C + c] = acc;
}

// ---------------------------------------------------------------------------
// Kernel 1b: sum local_f over nl*nf -> s_l[b][c]  (301 MB streaming read)
// ---------------------------------------------------------------------------
__global__ void sum_local_k(const float* __restrict__ lf) {
    int split = blockIdx.x;            // gridDim.x splits of the token range
    int b = blockIdx.y;
    int c = threadIdx.x;               // blockDim = C = 640 (coalesced per warp)
    int per = (NT + gridDim.x - 1) / gridDim.x;
    int t0 = split * per;
    int t1 = min(t0 + per, NT);
    const float* base = lf + ((size_t)b * NT) * C + c;
    float acc = 0.f;
    for (int t = t0; t < t1; ++t) acc += base[(size_t)t * C];
    atomicAdd(&g_scratch[OFF_SL + b * C + c], acc);
}

// ---------------------------------------------------------------------------
// Kernel 2: small projections.
//  rows 0..NG-1 : gproj[b][r] = Wq @ global_f[b][r]
//  row  NG      : m1[b]      = Wq @ s_g[b]
//  row  NG+1    : m2[b]      = Wk @ s_l[b]
// ---------------------------------------------------------------------------
__global__ void proj_k(const float* __restrict__ gf,
                       const float* __restrict__ Wq,
                       const float* __restrict__ Wk) {
    int r = blockIdx.x;   // 0..NG+1
    int b = blockIdx.y;
    __shared__ float xs[C];
    const float* x;
    const float* W;
    float* out;
    if (r < NG) {
        x = gf + (b * NG + r) * C; W = Wq;
        out = &g_scratch[OFF_GPROJ + (b * NG + r) * C];
    } else if (r == NG) {
        x = &g_scratch[OFF_SG + b * C]; W = Wq;
        out = &g_scratch[OFF_M1 + b * C];
    } else {
        x = &g_scratch[OFF_SL + b * C]; W = Wk;
        out = &g_scratch[OFF_M2 + b * C];
    }
    for (int c = threadIdx.x; c < C; c += blockDim.x) xs[c] = x[c];
    __syncthreads();
    for (int d = threadIdx.x; d < C; d += blockDim.x) {
        const float* wr = W + (size_t)d * C;
        float acc = 0.f;
#pragma unroll 8
        for (int c = 0; c < C; c++) acc += wr[c] * xs[c];
        out[d] = acc;
    }
}

// ---------------------------------------------------------------------------
// Kernel 3: mean = (m1+m2)/14705 ; ghat = l2norm(gproj - mean)
// one block per batch, blockDim = C = 640 (20 warps)
// ---------------------------------------------------------------------------
__global__ void meanghat_k() {
    int b = blockIdx.x;
    int c = threadIdx.x;
    __shared__ float red[32];
    float mean = (g_scratch[OFF_M1 + b * C + c] + g_scratch[OFF_M2 + b * C + c])
                 * (1.0f / (float)NMEAN_DEN);
    g_scratch[OFF_MEAN + b * C + c] = mean;
    for (int j = 0; j < NG; j++) {
        float v = g_scratch[OFF_GPROJ + (b * NG + j) * C + c] - mean;
        float s = v * v;
#pragma unroll
        for (int o = 16; o; o >>= 1) s += __shfl_xor_sync(0xffffffffu, s, o);
        if ((threadIdx.x & 31) == 0) red[threadIdx.x >> 5] = s;
        __syncthreads();
        if (threadIdx.x < 32) {
            float t = (threadIdx.x < (blockDim.x >> 5)) ? red[threadIdx.x] : 0.f;
#pragma unroll
            for (int o = 16; o; o >>= 1) t += __shfl_xor_sync(0xffffffffu, t, o);
            if (threadIdx.x == 0) red[0] = t;
        }
        __syncthreads();
        float inv = rsqrtf(red[0] + L2EPS);
        g_scratch[OFF_GHAT + (b * NG + j) * C + c] = v * inv;
        __syncthreads();   // red[] reused next j
    }
}

// ---------------------------------------------------------------------------
// Kernel 4: the heavy fused GEMM.
//  y[t][d] = sum_c Wk[d][c]*x[t][c] - mean[b][d]   (never stored to memory)
//  epilogue reduces per token:  norm2 += y^2 ;  dots[j] += y*ghat[j][d]
//  Tile: 128 tokens x 128 dims, BK=16, 256 threads, 8x8 per thread.
// ---------------------------------------------------------------------------
#define TM 128
#define TN 128
#define BK 16

__global__ __launch_bounds__(256, 2)
void gemm_k(const float* __restrict__ lf, const float* __restrict__ Wk) {
    int b  = blockIdx.z;
    int t0 = blockIdx.x * TM;
    int d0 = blockIdx.y * TN;
    int tid = threadIdx.x;
    int tx = tid & 15;        // 0..15 -> cols tx*8..tx*8+7
    int ty = tid >> 4;        // 0..15 -> rows ty*8..ty*8+7

    __shared__ float AsT[BK][TM + 4];
    __shared__ float BsT[BK][TN + 4];

    float acc[8][8];
#pragma unroll
    for (int r = 0; r < 8; r++)
#pragma unroll
        for (int cc = 0; cc < 8; cc++) acc[r][cc] = 0.f;

    const float* Ab = lf + (size_t)b * NT * C;

    for (int k0 = 0; k0 < C; k0 += BK) {
        // load A tile: 128 rows x 16 -> 512 float4, 2 per thread
#pragma unroll
        for (int i = 0; i < 2; i++) {
            int f = tid + i * 256;
            int row = f >> 2, seg = f & 3;
            int gr = t0 + row;
            float4 v = make_float4(0.f, 0.f, 0.f, 0.f);
            if (gr < NT) v = *(const float4*)(Ab + (size_t)gr * C + k0 + seg * 4);
            AsT[seg * 4 + 0][row] = v.x;
            AsT[seg * 4 + 1][row] = v.y;
            AsT[seg * 4 + 2][row] = v.z;
            AsT[seg * 4 + 3][row] = v.w;
        }
        // load B tile (Wk rows d0..d0+127): 512 float4, 2 per thread
#pragma unroll
        for (int i = 0; i < 2; i++) {
            int f = tid + i * 256;
            int dd = f >> 2, seg = f & 3;
            float4 v = *(const float4*)(Wk + (size_t)(d0 + dd) * C + k0 + seg * 4);
            BsT[seg * 4 + 0][dd] = v.x;
            BsT[seg * 4 + 1][dd] = v.y;
            BsT[seg * 4 + 2][dd] = v.z;
            BsT[seg * 4 + 3][dd] = v.w;
        }
        __syncthreads();
#pragma unroll
        for (int kk = 0; kk < BK; kk++) {
            float4 a0 = *(const float4*)&AsT[kk][ty * 8];
            float4 a1 = *(const float4*)&AsT[kk][ty * 8 + 4];
            float4 b0 = *(const float4*)&BsT[kk][tx * 8];
            float4 b1 = *(const float4*)&BsT[kk][tx * 8 + 4];
            float av[8] = {a0.x, a0.y, a0.z, a0.w, a1.x, a1.y, a1.z, a1.w};
            float bv[8] = {b0.x, b0.y, b0.z, b0.w, b1.x, b1.y, b1.z, b1.w};
#pragma unroll
            for (int r = 0; r < 8; r++)
#pragma unroll
                for (int cc = 0; cc < 8; cc++) acc[r][cc] += av[r] * bv[cc];
        }
        __syncthreads();
    }

    // ---- epilogue: per-token reductions over this d-chunk ----
    int dbase = d0 + tx * 8;
    float mn[8], gh[NG][8];
#pragma unroll
    for (int cc = 0; cc < 8; cc++) mn[cc] = g_scratch[OFF_MEAN + b * C + dbase + cc];
#pragma unroll
    for (int jj = 0; jj < NG; jj++)
#pragma unroll
        for (int cc = 0; cc < 8; cc++)
            gh[jj][cc] = g_scratch[OFF_GHAT + (b * NG + jj) * C + dbase + cc];

#pragma unroll
    for (int r = 0; r < 8; r++) {
        int row = t0 + ty * 8 + r;
        float y[8];
#pragma unroll
        for (int cc = 0; cc < 8; cc++) y[cc] = acc[r][cc] - mn[cc];
        float ps = 0.f;
        float pd[NG] = {0.f, 0.f, 0.f, 0.f, 0.f};
#pragma unroll
        for (int cc = 0; cc < 8; cc++) {
            ps += y[cc] * y[cc];
#pragma unroll
            for (int jj = 0; jj < NG; jj++) pd[jj] += y[cc] * gh[jj][cc];
        }
        // reduce across the 16 tx lanes (xor <=8 stays inside each 16-lane half)
#pragma unroll
        for (int o = 8; o; o >>= 1) {
            ps += __shfl_xor_sync(0xffffffffu, ps, o);
#pragma unroll
            for (int jj = 0; jj < NG; jj++)
                pd[jj] += __shfl_xor_sync(0xffffffffu, pd[jj], o);
        }
        if (tx == 0 && row < NT) {
            atomicAdd(&g_scratch[OFF_NORM2 + b * NT + row], ps);
            float* dp = &g_scratch[OFF_DOTS + ((size_t)b * NT + row) * NG];
#pragma unroll
            for (int jj = 0; jj < NG; jj++) atomicAdd(dp + jj, pd[jj]);
        }
    }
}

// ---------------------------------------------------------------------------
// Kernel 5: scores + softmax over nf, write output [b,nl,ng,nf,1]
// grid (NG, NL, B), 256 threads (196 active)
// ---------------------------------------------------------------------------
__global__ void softmax_k(float* __restrict__ out) {
    int j = blockIdx.x, l = blockIdx.y, b = blockIdx.z;
    int f = threadIdx.x;
    __shared__ float red[8];

    float s = -1e30f;
    if (f < NF) {
        int t = l * NF + f;
        float n2 = g_scratch[OFF_NORM2 + b * NT + t];
        float d  = g_scratch[OFF_DOTS + ((size_t)b * NT + t) * NG + j];
        s = d * rsqrtf(n2 + L2EPS) * INV_ALPHA;
    }
    // block max
    float m = s;
#pragma unroll
    for (int o = 16; o; o >>= 1) m = fmaxf(m, __shfl_xor_sync(0xffffffffu, m, o));
    if ((threadIdx.x & 31) == 0) red[threadIdx.x >> 5] = m;
    __syncthreads();
    m = red[0];
#pragma unroll
    for (int w = 1; w < 8; w++) m = fmaxf(m, red[w]);

    float e = (f < NF) ? expf(s - m) : 0.f;
    float sum = e;
#pragma unroll
    for (int o = 16; o; o >>= 1) sum += __shfl_xor_sync(0xffffffffu, sum, o);
    __syncthreads();
    if ((threadIdx.x & 31) == 0) red[threadIdx.x >> 5] = sum;
    __syncthreads();
    sum = 0.f;
#pragma unroll
    for (int w = 0; w < 8; w++) sum += red[w];

    if (f < NF)
        out[(((size_t)b * NL + l) * NG + j) * NF + f] = e / sum;
}

// ---------------------------------------------------------------------------
extern "C" void kernel_launch(void* const* d_in, const int* in_sizes, int n_in,
                              void* d_out, int out_size) {
    const float* gf = (const float*)d_in[0];   // global_f [8,5,640]
    const float* lf = (const float*)d_in[1];   // local_f  [8,75,196,640]
    const float* Wq = (const float*)d_in[2];   // [640,640]
    const float* Wk = (const float*)d_in[3];   // [640,640]
    float* out = (float*)d_out;                // [8,75,5,196,1]

    zero_k<<<256, 256>>>();
    sum_global_k<<<B, C>>>(gf);
    sum_local_k<<<dim3(50, B), C>>>(lf);
    proj_k<<<dim3(NG + 2, B), 128>>>(gf, Wq, Wk);
    meanghat_k<<<B, C>>>();
    gemm_k<<<dim3((NT + TM - 1) / TM, C / TN, B), 256>>>(lf, Wk);
    softmax_k<<<dim3(NG, NL, B), 256>>>(out);
}

// round 6
// speedup vs baseline: 2.8440x; 2.8440x over previous
#include <cuda_runtime.h>
#include <math.h>
#include <stdint.h>

#define B   8
#define NG  5
#define NL  75
#define NF  196
#define C   640
#define NT  (NL*NF)
#define NMEAN_DEN (NG + NT)
#define INV_ALPHA 10.0f
#define L2EPS 1e-12f

#define OFF_SG     0
#define OFF_SL     (OFF_SG + B*C)
#define OFF_GPROJ  (OFF_SL + B*C)
#define OFF_M1     (OFF_GPROJ + B*NG*C)
#define OFF_M2     (OFF_M1 + B*C)
#define OFF_MEAN   (OFF_M2 + B*C)
#define OFF_GHAT   (OFF_MEAN + B*C)
#define OFF_NORM2  (OFF_GHAT + B*NG*C)
#define OFF_DOTS   (OFF_NORM2 + B*NT)
#define SCRATCH_FLOATS (OFF_DOTS + B*NT*NG)

__device__ __align__(16) float g_scratch[SCRATCH_FLOATS];

// ---------------- helpers ----------------
__device__ __forceinline__ uint32_t smem_u32(const void* p) {
    uint32_t a;
    asm("{ .reg .u64 t; cvta.to.shared.u64 t, %1; cvt.u32.u64 %0, t; }" : "=r"(a) : "l"(p));
    return a;
}
__device__ __forceinline__ void cpa16(uint32_t dst, const void* src) {
    asm volatile("cp.async.cg.shared.global [%0], [%1], 16;" :: "r"(dst), "l"(src));
}
__device__ __forceinline__ void mma_tf32(float* d, const uint32_t* a, const uint32_t* b) {
    asm volatile(
        "mma.sync.aligned.m16n8k8.row.col.f32.tf32.tf32.f32 "
        "{%0,%1,%2,%3}, {%4,%5,%6,%7}, {%8,%9}, {%0,%1,%2,%3};"
        : "+f"(d[0]), "+f"(d[1]), "+f"(d[2]), "+f"(d[3])
        : "r"(a[0]), "r"(a[1]), "r"(a[2]), "r"(a[3]), "r"(b[0]), "r"(b[1]));
}

// ---------------- small kernels ----------------
// zero EVERY atomically-accumulated region: SL sums + NORM2 + DOTS
__global__ void zero_k() {
    int i = blockIdx.x * blockDim.x + threadIdx.x;
    if (i < B * C) g_scratch[OFF_SL + i] = 0.f;
    if (i < B * NT * (1 + NG)) g_scratch[OFF_NORM2 + i] = 0.f;
}

__global__ void sum_global_k(const float* __restrict__ gf) {
    int b = blockIdx.x, c = threadIdx.x;  // blockDim=640
    float acc = 0.f;
#pragma unroll
    for (int g = 0; g < NG; g++) acc += gf[(b * NG + g) * C + c];
    g_scratch[OFF_SG + b * C + c] = acc;
}

__global__ void sum_local_k(const float* __restrict__ lf) {
    int split = blockIdx.x, b = blockIdx.y, c = threadIdx.x;  // blockDim=640
    int per = (NT + gridDim.x - 1) / gridDim.x;
    int t0 = split * per, t1 = min(t0 + per, NT);
    const float* base = lf + ((size_t)b * NT) * C + c;
    float acc = 0.f;
    for (int t = t0; t < t1; ++t) acc += base[(size_t)t * C];
    atomicAdd(&g_scratch[OFF_SL + b * C + c], acc);
}

// coalesced warp-per-row projection; grid (NG+2, B, 4), 256 thr
__global__ void proj_k(const float* __restrict__ gf,
                       const float* __restrict__ Wq,
                       const float* __restrict__ Wk) {
    int r = blockIdx.x, b = blockIdx.y, ds = blockIdx.z;
    __shared__ float xs[C];
    const float* x; const float* W; float* out;
    if (r < NG)       { x = gf + (b * NG + r) * C;      W = Wq; out = &g_scratch[OFF_GPROJ + (b * NG + r) * C]; }
    else if (r == NG) { x = &g_scratch[OFF_SG + b * C]; W = Wq; out = &g_scratch[OFF_M1 + b * C]; }
    else              { x = &g_scratch[OFF_SL + b * C]; W = Wk; out = &g_scratch[OFF_M2 + b * C]; }
    for (int c = threadIdx.x; c < C; c += blockDim.x) xs[c] = x[c];
    __syncthreads();
    int w = threadIdx.x >> 5, lane = threadIdx.x & 31;
    for (int d = ds * 160 + w; d < (ds + 1) * 160; d += 8) {
        const float* wr = W + (size_t)d * C;
        float a = 0.f;
        for (int c = lane; c < C; c += 32) a += wr[c] * xs[c];
#pragma unroll
        for (int o = 16; o; o >>= 1) a += __shfl_xor_sync(0xffffffffu, a, o);
        if (lane == 0) out[d] = a;
    }
}

__global__ void meanghat_k() {
    int b = blockIdx.x, c = threadIdx.x;  // blockDim=640
    __shared__ float red[32];
    float mean = (g_scratch[OFF_M1 + b * C + c] + g_scratch[OFF_M2 + b * C + c])
                 * (1.0f / (float)NMEAN_DEN);
    g_scratch[OFF_MEAN + b * C + c] = mean;
    for (int j = 0; j < NG; j++) {
        float v = g_scratch[OFF_GPROJ + (b * NG + j) * C + c] - mean;
        float s = v * v;
#pragma unroll
        for (int o = 16; o; o >>= 1) s += __shfl_xor_sync(0xffffffffu, s, o);
        if ((threadIdx.x & 31) == 0) red[threadIdx.x >> 5] = s;
        __syncthreads();
        if (threadIdx.x < 32) {
            float t = (threadIdx.x < 20) ? red[threadIdx.x] : 0.f;
#pragma unroll
            for (int o = 16; o; o >>= 1) t += __shfl_xor_sync(0xffffffffu, t, o);
            if (threadIdx.x == 0) red[0] = t;
        }
        __syncthreads();
        float inv = rsqrtf(red[0] + L2EPS);
        g_scratch[OFF_GHAT + (b * NG + j) * C + c] = v * inv;
        __syncthreads();
    }
}

// ---------------- tf32 mma.sync GEMM ----------------
// Tile 128x128x16, 8 warps (2x4), warp tile 64x32 (4 m16 x 4 n8).
// smem rows: [row][20 floats] (16 data + 4 pad) -> conflict-free frag LDS.
#define BM 128
#define BN 128
#define BK 16
#define ROWF 20                          // floats per smem row
#define STAGE_FLOATS (2*BM*ROWF)         // A then B, 5120 floats
#define STG 3
#define EG_OFF (STG*STAGE_FLOATS)        // 15360: eg[6][128]
#define RA_OFF (EG_OFF + 6*BN)           // rowacc[128][6]
#define GSMEM_FLOATS (RA_OFF + BM*6)
#define NITER (C/BK)                     // 40

__device__ __forceinline__ void load_tile(int it, int stage, uint32_t sb,
                                          const float* lfb, const float* Wk,
                                          int t0, int d0, int tid) {
    uint32_t ab = sb + stage * (STAGE_FLOATS * 4);
    uint32_t bb = ab + BM * ROWF * 4;
    int seg = tid & 3;            // 16B chunk within 64B row
    int r0 = tid >> 2;            // 0..63
    int k0 = it * BK;
#pragma unroll
    for (int h = 0; h < 2; h++) {
        int row = r0 + h * 64;
        int tok = t0 + row; if (tok >= NT) tok = NT - 1;
        cpa16(ab + (row * ROWF + seg * 4) * 4, lfb + (size_t)tok * C + k0 + seg * 4);
        cpa16(bb + (row * ROWF + seg * 4) * 4, Wk + (size_t)(d0 + row) * C + k0 + seg * 4);
    }
    asm volatile("cp.async.commit_group;" ::: "memory");
}

__global__ __launch_bounds__(256, 2)
void gemm_mma_k(const float* __restrict__ lf, const float* __restrict__ Wk) {
    extern __shared__ __align__(16) float sm[];
    uint32_t sb = smem_u32(sm);
    int tid = threadIdx.x, wid = tid >> 5, lane = tid & 31;
    int g = lane >> 2, t = lane & 3;
    int wm = wid >> 2, wn = wid & 3;     // 2 x 4 warp grid
    int chunk = blockIdx.x, b = blockIdx.z;
    int t0 = blockIdx.y * BM;
    int d0 = chunk * BN;
    const float* lfb = lf + (size_t)b * NT * C;

    float acc[4][4][4];
#pragma unroll
    for (int mt = 0; mt < 4; mt++)
#pragma unroll
        for (int nt = 0; nt < 4; nt++)
#pragma unroll
            for (int cc = 0; cc < 4; cc++) acc[mt][nt][cc] = 0.f;

    load_tile(0, 0, sb, lfb, Wk, t0, d0, tid);
    load_tile(1, 1, sb, lfb, Wk, t0, d0, tid);

    for (int it = 0; it < NITER; it++) {
        int s = it % STG;
        asm volatile("cp.async.wait_group 1;" ::: "memory");
        __syncthreads();
        if (it + 2 < NITER) load_tile(it + 2, (it + 2) % STG, sb, lfb, Wk, t0, d0, tid);

        const float* As = sm + s * STAGE_FLOATS;
        const float* Bs = As + BM * ROWF;
        int am0 = wm * 64 + g;
        int bn0 = wn * 32 + g;
#pragma unroll
        for (int kk = 0; kk < 2; kk++) {
            int kc = kk * 8 + t;
            uint32_t af[4][4], bf[4][2];
#pragma unroll
            for (int mt = 0; mt < 4; mt++) {
                int r = am0 + mt * 16;
                af[mt][0] = __float_as_uint(As[r * ROWF + kc]);
                af[mt][1] = __float_as_uint(As[(r + 8) * ROWF + kc]);
                af[mt][2] = __float_as_uint(As[r * ROWF + kc + 4]);
                af[mt][3] = __float_as_uint(As[(r + 8) * ROWF + kc + 4]);
            }
#pragma unroll
            for (int nt = 0; nt < 4; nt++) {
                int n = bn0 + nt * 8;
                bf[nt][0] = __float_as_uint(Bs[n * ROWF + kc]);
                bf[nt][1] = __float_as_uint(Bs[n * ROWF + kc + 4]);
            }
#pragma unroll
            for (int mt = 0; mt < 4; mt++)
#pragma unroll
                for (int nt = 0; nt < 4; nt++)
                    mma_tf32(acc[mt][nt], af[mt], bf[nt]);
        }
        __syncthreads();
    }
    asm volatile("cp.async.wait_group 0;" ::: "memory");

    // ---- epilogue ----
    float* eg = sm + EG_OFF;       // eg[j][128], j=0..4 ghat, j=5 mean
    float* ra = sm + RA_OFF;       // rowacc[128][6]
    for (int idx = tid; idx < 6 * BN; idx += 256) {
        int j = idx >> 7, c = idx & 127;
        eg[idx] = (j < 5) ? g_scratch[OFF_GHAT + (b * NG + j) * C + d0 + c]
                          : g_scratch[OFF_MEAN + b * C + d0 + c];
    }
    for (int idx = tid; idx < BM * 6; idx += 256) ra[idx] = 0.f;
    __syncthreads();

#pragma unroll
    for (int mt = 0; mt < 4; mt++) {
#pragma unroll
        for (int rv = 0; rv < 2; rv++) {
            int row = wm * 64 + mt * 16 + g + rv * 8;
            float v[6] = {0.f, 0.f, 0.f, 0.f, 0.f, 0.f};
#pragma unroll
            for (int nt = 0; nt < 4; nt++) {
#pragma unroll
                for (int cc = 0; cc < 2; cc++) {
                    int col = wn * 32 + nt * 8 + 2 * t + cc;
                    float z = acc[mt][nt][rv * 2 + cc] - eg[5 * BN + col];
                    v[0] = fmaf(z, z, v[0]);
#pragma unroll
                    for (int j = 0; j < NG; j++)
                        v[1 + j] = fmaf(z, eg[j * BN + col], v[1 + j]);
                }
            }
#pragma unroll
            for (int j = 0; j < 6; j++) {
                v[j] += __shfl_xor_sync(0xffffffffu, v[j], 1);
                v[j] += __shfl_xor_sync(0xffffffffu, v[j], 2);
            }
            if (t == 0) {
#pragma unroll
                for (int j = 0; j < 6; j++) atomicAdd(&ra[row * 6 + j], v[j]);
            }
        }
    }
    __syncthreads();

    for (int row = tid; row < BM; row += 256) {
        int tok = t0 + row;
        if (tok < NT) {
            atomicAdd(&g_scratch[OFF_NORM2 + b * NT + tok], ra[row * 6]);
            float* dp = &g_scratch[OFF_DOTS + ((size_t)b * NT + tok) * NG];
#pragma unroll
            for (int j = 0; j < NG; j++) atomicAdd(dp + j, ra[row * 6 + 1 + j]);
        }
    }
}

// ---------------- softmax ----------------
__global__ void softmax_k(float* __restrict__ out) {
    int j = blockIdx.x, l = blockIdx.y, b = blockIdx.z;
    int f = threadIdx.x;
    __shared__ float red[8];
    float s = -1e30f;
    if (f < NF) {
        int t = l * NF + f;
        float n2 = g_scratch[OFF_NORM2 + b * NT + t];
        float d  = g_scratch[OFF_DOTS + ((size_t)b * NT + t) * NG + j];
        s = d * rsqrtf(n2 + L2EPS) * INV_ALPHA;
    }
    float m = s;
#pragma unroll
    for (int o = 16; o; o >>= 1) m = fmaxf(m, __shfl_xor_sync(0xffffffffu, m, o));
    if ((threadIdx.x & 31) == 0) red[threadIdx.x >> 5] = m;
    __syncthreads();
    m = red[0];
#pragma unroll
    for (int w = 1; w < 8; w++) m = fmaxf(m, red[w]);
    float e = (f < NF) ? expf(s - m) : 0.f;
    float sum = e;
#pragma unroll
    for (int o = 16; o; o >>= 1) sum += __shfl_xor_sync(0xffffffffu, sum, o);
    __syncthreads();
    if ((threadIdx.x & 31) == 0) red[threadIdx.x >> 5] = sum;
    __syncthreads();
    sum = 0.f;
#pragma unroll
    for (int w = 0; w < 8; w++) sum += red[w];
    if (f < NF)
        out[(((size_t)b * NL + l) * NG + j) * NF + f] = e / sum;
}

// ---------------------------------------------------------------------------
extern "C" void kernel_launch(void* const* d_in, const int* in_sizes, int n_in,
                              void* d_out, int out_size) {
    const float* gf = (const float*)d_in[0];
    const float* lf = (const float*)d_in[1];
    const float* Wq = (const float*)d_in[2];
    const float* Wk = (const float*)d_in[3];
    float* out = (float*)d_out;

    // unconditional (no static guards — harness contract); host-side, capture-safe
    cudaFuncSetAttribute(gemm_mma_k, cudaFuncAttributeMaxDynamicSharedMemorySize,
                         GSMEM_FLOATS * 4);

    zero_k<<<(B * NT * (1 + NG) + 255) / 256, 256>>>();
    sum_global_k<<<B, C>>>(gf);
    sum_local_k<<<dim3(120, B), C>>>(lf);
    proj_k<<<dim3(NG + 2, B, 4), 256>>>(gf, Wq, Wk);
    meanghat_k<<<B, C>>>();
    gemm_mma_k<<<dim3(C / BN, (NT + BM - 1) / BM, B), 256, GSMEM_FLOATS * 4>>>(lf, Wk);
    softmax_k<<<dim3(NG, NL, B), 256>>>(out);
}